// round 11
// baseline (speedup 1.0000x reference)
#include <cuda_runtime.h>
#include <cuda_bf16.h>
#include <cstdint>

#define E_   16
#define KSEL 2
#define DIM  1024
#define FF   512
#define TOK  4096
#define TKN  (TOK * KSEL)
#define CAP  2048          // per-expert capacity (matches reference C)

// ---------------- device scratch ----------------------------------------------
__device__ int g_off[E_ + 1];
__device__ int g_tok[TKN];
__device__ int g_pos[TKN];          // flat slot -> compacted pos, -1 if dropped
__device__ __align__(16) __nv_bfloat16 g_xhi[(size_t)TOK * DIM];
__device__ __align__(16) __nv_bfloat16 g_xlo[(size_t)TOK * DIM];
__device__ __align__(16) __nv_bfloat16 g_wgThi[(size_t)E_ * FF * DIM];
__device__ __align__(16) __nv_bfloat16 g_wgTlo[(size_t)E_ * FF * DIM];
__device__ __align__(16) __nv_bfloat16 g_wuThi[(size_t)E_ * FF * DIM];
__device__ __align__(16) __nv_bfloat16 g_wuTlo[(size_t)E_ * FF * DIM];
__device__ __align__(16) __nv_bfloat16 g_wdThi[(size_t)E_ * DIM * FF];
__device__ __align__(16) __nv_bfloat16 g_wdTlo[(size_t)E_ * DIM * FF];
__device__ __align__(16) __nv_bfloat16 g_hhi[(size_t)TKN * FF];
__device__ __align__(16) __nv_bfloat16 g_hlo[(size_t)TKN * FF];
__device__ __align__(16) float g_y[(size_t)TKN * DIM];

// ---------------- helpers -------------------------------------------------------
__device__ __forceinline__ uint32_t smem_u32(const void* p) {
    uint32_t a;
    asm("{ .reg .u64 t; cvta.to.shared.u64 t, %1; cvt.u32.u64 %0, t; }" : "=r"(a) : "l"(p));
    return a;
}
__device__ __forceinline__ void cpa16(uint32_t sm, const void* g) {
    asm volatile("cp.async.ca.shared.global [%0], [%1], 16;" :: "r"(sm), "l"(g));
}
#define CPA_COMMIT() asm volatile("cp.async.commit_group;" ::: "memory")
#define CPA_WAIT1()  asm volatile("cp.async.wait_group 1;" ::: "memory")

__device__ __forceinline__ void ldm4(uint32_t* r, uint32_t addr) {
    asm volatile("ldmatrix.sync.aligned.m8n8.x4.shared.b16 {%0,%1,%2,%3}, [%4];"
                 : "=r"(r[0]), "=r"(r[1]), "=r"(r[2]), "=r"(r[3]) : "r"(addr));
}
__device__ __forceinline__ void mma16816(float* c, const uint32_t* a, const uint32_t* b) {
    asm volatile(
        "mma.sync.aligned.m16n8k16.row.col.f32.bf16.bf16.f32 "
        "{%0,%1,%2,%3}, {%4,%5,%6,%7}, {%8,%9}, {%0,%1,%2,%3};"
        : "+f"(c[0]), "+f"(c[1]), "+f"(c[2]), "+f"(c[3])
        : "r"(a[0]), "r"(a[1]), "r"(a[2]), "r"(a[3]), "r"(b[0]), "r"(b[1]));
}
__device__ __forceinline__ uint32_t pack2(__nv_bfloat16 a, __nv_bfloat16 b) {
    return (uint32_t)__bfloat16_as_ushort(a) | ((uint32_t)__bfloat16_as_ushort(b) << 16);
}
// 64B-row tile swizzle: granule col (16B units, 0..3) XOR (row>>1)&3
__device__ __forceinline__ uint32_t soff(int row, int c) {
    return (uint32_t)(row * 64 + ((c ^ ((row >> 1) & 3)) * 16));
}

// ---------------- fused dispatch (single CTA) -----------------------------------
__global__ void k_dispatch(const int* __restrict__ w32) {
    __shared__ int s_acc;
    __shared__ int s_cnt[E_];
    __shared__ int s_off[E_ + 1];
    __shared__ int s_cur[E_];
    int tid = threadIdx.x;

    if (tid == 0) s_acc = 0;
    if (tid < E_) s_cnt[tid] = 0;
    __syncthreads();

    int o = 0;
    for (int i = tid; i < TKN / 2; i += blockDim.x) o |= w32[2 * i + 1];
    atomicOr(&s_acc, o);
    __syncthreads();
    int is64 = (s_acc == 0) ? 1 : 0;

    for (int s = tid; s < TKN; s += blockDim.x) {
        int e = (is64 ? w32[2 * s] : w32[s]) & (E_ - 1);
        atomicAdd(&s_cnt[e], 1);
    }
    __syncthreads();

    if (tid == 0) {
        int acc = 0;
        for (int e = 0; e < E_; e++) {
            s_off[e] = acc;
            s_cur[e] = acc;
            g_off[e] = acc;
            acc += s_cnt[e];
        }
        s_off[E_] = acc;
        g_off[E_] = acc;
    }
    __syncthreads();

    for (int s = tid; s < TKN; s += blockDim.x) {
        int e = (is64 ? w32[2 * s] : w32[s]) & (E_ - 1);
        int p = atomicAdd(&s_cur[e], 1);
        g_tok[p] = s / KSEL;
        g_pos[s] = (p - s_off[e] < CAP) ? p : -1;
    }
}

// ---------------- conversions ---------------------------------------------------
__global__ void k_cvt_x(const float4* __restrict__ x) {
    int i = blockIdx.x * blockDim.x + threadIdx.x;
    float4 v = x[i];
    __nv_bfloat16 h0 = __float2bfloat16(v.x), h1 = __float2bfloat16(v.y),
                  h2 = __float2bfloat16(v.z), h3 = __float2bfloat16(v.w);
    __nv_bfloat16 l0 = __float2bfloat16(v.x - __bfloat162float(h0));
    __nv_bfloat16 l1 = __float2bfloat16(v.y - __bfloat162float(h1));
    __nv_bfloat16 l2 = __float2bfloat16(v.z - __bfloat162float(h2));
    __nv_bfloat16 l3 = __float2bfloat16(v.w - __bfloat162float(h3));
    ((uint2*)g_xhi)[i] = make_uint2(pack2(h0, h1), pack2(h2, h3));
    ((uint2*)g_xlo)[i] = make_uint2(pack2(l0, l1), pack2(l2, l3));
}

__global__ void k_cvt_w(const float* __restrict__ wg, const float* __restrict__ wu,
                        const float* __restrict__ wd) {
    int z = blockIdx.z, m = z >> 4, e = z & 15;
    int R = (m == 2) ? FF : DIM;
    int C = (m == 2) ? DIM : FF;
    const float* src = (m == 0 ? wg : m == 1 ? wu : wd) + (size_t)e * DIM * FF;
    __nv_bfloat16* dh = (m == 0 ? g_wgThi : m == 1 ? g_wuThi : g_wdThi) + (size_t)e * DIM * FF;
    __nv_bfloat16* dl = (m == 0 ? g_wgTlo : m == 1 ? g_wuTlo : g_wdTlo) + (size_t)e * DIM * FF;
    int c0 = blockIdx.x * 32, r0 = blockIdx.y * 32;
    if (c0 >= C || r0 >= R) return;
    __shared__ float t[32][33];
    int tx = threadIdx.x, ty = threadIdx.y;
#pragma unroll
    for (int i = 0; i < 4; i++)
        t[ty + i * 8][tx] = src[(size_t)(r0 + ty + i * 8) * C + c0 + tx];
    __syncthreads();
#pragma unroll
    for (int i = 0; i < 4; i++) {
        float v = t[tx][ty + i * 8];
        __nv_bfloat16 h = __float2bfloat16(v);
        __nv_bfloat16 l = __float2bfloat16(v - __bfloat162float(h));
        size_t o = (size_t)(c0 + ty + i * 8) * R + r0 + tx;
        dh[o] = h;
        dl[o] = l;
    }
}

// ---------------- GEMM1: h = silu(X Wg)*(X Wu), bf16x3 HMMA, BK=32 --------------
// stage (32KB): Ahi 8K | Alo 8K | Bgh 4K | Bgl 4K | Buh 4K | Bul 4K  (64B rows)
#define STG1 32768
__global__ __launch_bounds__(256, 2) void k_gemm1() {
    extern __shared__ __align__(16) char dsm[];

    int e = blockIdx.z;
    int base = g_off[e], ne = g_off[e + 1] - base;
    int m0 = blockIdx.y * 128;
    if (m0 >= ne) return;
    int n0 = blockIdx.x * 64;

    int tid = threadIdx.x, lane = tid & 31, wid = tid >> 5;
    int wm = wid >> 1, wn = wid & 1;

    size_t wb = ((size_t)e * FF + n0) * DIM;
    const __nv_bfloat16* wgh = g_wgThi + wb;
    const __nv_bfloat16* wgl = g_wgTlo + wb;
    const __nv_bfloat16* wuh = g_wuThi + wb;
    const __nv_bfloat16* wul = g_wuTlo + wb;

    // A loads: thread t -> row t>>1, granules c0=(t&1)*2 and c0+1
    int arow = tid >> 1, ac0 = (tid & 1) * 2;
    int arr = m0 + arow; if (arr >= ne) arr = ne - 1;
    size_t tokrow = (size_t)g_tok[base + arr] * DIM;
    uint32_t sa0 = soff(arow, ac0), sa1 = soff(arow, ac0 + 1);
    // B loads: thread t -> row t>>2, granule t&3 (one per matrix)
    int brow = tid >> 2, bc = tid & 3;
    uint32_t sbo = soff(brow, bc);
    size_t gbo = (size_t)brow * DIM + bc * 8;

    uint32_t sb_base = smem_u32(dsm);
    auto ldstage = [&](int s, int it) {
        uint32_t sb = sb_base + s * STG1;
        int k0 = it * 32;
        cpa16(sb + sa0, g_xhi + tokrow + k0 + ac0 * 8);
        cpa16(sb + sa1, g_xhi + tokrow + k0 + ac0 * 8 + 8);
        cpa16(sb + 8192 + sa0, g_xlo + tokrow + k0 + ac0 * 8);
        cpa16(sb + 8192 + sa1, g_xlo + tokrow + k0 + ac0 * 8 + 8);
        cpa16(sb + 16384 + sbo, wgh + gbo + k0);
        cpa16(sb + 20480 + sbo, wgl + gbo + k0);
        cpa16(sb + 24576 + sbo, wuh + gbo + k0);
        cpa16(sb + 28672 + sbo, wul + gbo + k0);
    };

    float acc_g[2][4][4] = {};
    float acc_u[2][4][4] = {};

    ldstage(0, 0); CPA_COMMIT();
    ldstage(1, 1); CPA_COMMIT();

    const int NIT = DIM / 32;
    // fragment addressing
    int rowA = wm * 32 + (lane & 15);             // + mt*16
    int cA   = lane >> 4;                          // + 2*kk
    int rowB = wn * 32 + ((lane >> 4) << 3) + (lane & 7);   // + half*16
    int cB   = (lane >> 3) & 1;                    // + 2*kk
    int swA  = (rowA >> 1) & 3;                    // invariant under +16 rows
    int swB  = (rowB >> 1) & 3;

    int s = 0;
    for (int it = 0; it < NIT; it++) {
        CPA_WAIT1();
        __syncthreads();

        if (it + 2 < NIT) ldstage((s + 2 >= 3 ? s - 1 : s + 2), it + 2);
        CPA_COMMIT();

        uint32_t sb = sb_base + s * STG1;
#pragma unroll
        for (int kk = 0; kk < 2; kk++) {
            uint32_t caA = (uint32_t)(((2 * kk + cA) ^ swA) * 16);
            uint32_t ah[2][4], al[2][4];
            ldm4(ah[0], sb + (uint32_t)(rowA * 64) + caA);
            ldm4(ah[1], sb + (uint32_t)((rowA + 16) * 64) + caA);
            ldm4(al[0], sb + 8192 + (uint32_t)(rowA * 64) + caA);
            ldm4(al[1], sb + 8192 + (uint32_t)((rowA + 16) * 64) + caA);

            uint32_t caB = (uint32_t)(((2 * kk + cB) ^ swB) * 16);
#pragma unroll
            for (int half = 0; half < 2; half++) {
                uint32_t bo = (uint32_t)((rowB + half * 16) * 64) + caB;
                uint32_t bgh[4], bgl[4], buh[4], bul[4];
                ldm4(bgh, sb + 16384 + bo);
                ldm4(bgl, sb + 20480 + bo);
                ldm4(buh, sb + 24576 + bo);
                ldm4(bul, sb + 28672 + bo);
#pragma unroll
                for (int mt = 0; mt < 2; mt++)
#pragma unroll
                    for (int q = 0; q < 2; q++) {
                        int nt = half * 2 + q;
                        mma16816(acc_g[mt][nt], ah[mt], &bgh[q * 2]);
                        mma16816(acc_g[mt][nt], ah[mt], &bgl[q * 2]);
                        mma16816(acc_g[mt][nt], al[mt], &bgh[q * 2]);
                        mma16816(acc_u[mt][nt], ah[mt], &buh[q * 2]);
                        mma16816(acc_u[mt][nt], ah[mt], &bul[q * 2]);
                        mma16816(acc_u[mt][nt], al[mt], &buh[q * 2]);
                    }
            }
        }
        s = (s + 1 == 3) ? 0 : s + 1;
    }

#pragma unroll
    for (int mt = 0; mt < 2; mt++)
#pragma unroll
        for (int nt = 0; nt < 4; nt++) {
            int col = n0 + wn * 32 + nt * 8 + 2 * (lane & 3);
#pragma unroll
            for (int rp = 0; rp < 2; rp++) {
                int tr = wm * 32 + mt * 16 + (lane >> 2) + rp * 8;
                if (m0 + tr < ne) {
                    float gg0 = acc_g[mt][nt][rp * 2], gg1 = acc_g[mt][nt][rp * 2 + 1];
                    float uu0 = acc_u[mt][nt][rp * 2], uu1 = acc_u[mt][nt][rp * 2 + 1];
                    float h0 = gg0 / (1.f + __expf(-gg0)) * uu0;
                    float h1 = gg1 / (1.f + __expf(-gg1)) * uu1;
                    __nv_bfloat16 h0h = __float2bfloat16(h0);
                    __nv_bfloat16 h1h = __float2bfloat16(h1);
                    __nv_bfloat16 h0l = __float2bfloat16(h0 - __bfloat162float(h0h));
                    __nv_bfloat16 h1l = __float2bfloat16(h1 - __bfloat162float(h1h));
                    size_t o = (size_t)(base + m0 + tr) * FF + col;
                    *(uint32_t*)(g_hhi + o) = pack2(h0h, h1h);
                    *(uint32_t*)(g_hlo + o) = pack2(h0l, h1l);
                }
            }
        }
}

// ---------------- GEMM2: y = h Wd, bf16x3 HMMA, BK=32 ---------------------------
// stage (24KB): Ahi 8K | Alo 8K | Bh 4K | Bl 4K
#define STG2 24576
__global__ __launch_bounds__(256, 2) void k_gemm2() {
    extern __shared__ __align__(16) char dsm[];

    int e = blockIdx.z;
    int base = g_off[e], ne = g_off[e + 1] - base;
    int m0 = blockIdx.y * 128;
    if (m0 >= ne) return;
    int n0 = blockIdx.x * 64;

    int tid = threadIdx.x, lane = tid & 31, wid = tid >> 5;
    int wm = wid >> 1, wn = wid & 1;

    size_t wb = ((size_t)e * DIM + n0) * FF;
    const __nv_bfloat16* wdh = g_wdThi + wb;
    const __nv_bfloat16* wdl = g_wdTlo + wb;

    int arow = tid >> 1, ac0 = (tid & 1) * 2;
    int arr = m0 + arow; if (arr >= ne) arr = ne - 1;
    size_t hrow = (size_t)(base + arr) * FF;
    uint32_t sa0 = soff(arow, ac0), sa1 = soff(arow, ac0 + 1);
    int brow = tid >> 2, bc = tid & 3;
    uint32_t sbo = soff(brow, bc);
    size_t gbo = (size_t)brow * FF + bc * 8;

    uint32_t sb_base = smem_u32(dsm);
    auto ldstage = [&](int s, int it) {
        uint32_t sb = sb_base + s * STG2;
        int k0 = it * 32;
        cpa16(sb + sa0, g_hhi + hrow + k0 + ac0 * 8);
        cpa16(sb + sa1, g_hhi + hrow + k0 + ac0 * 8 + 8);
        cpa16(sb + 8192 + sa0, g_hlo + hrow + k0 + ac0 * 8);
        cpa16(sb + 8192 + sa1, g_hlo + hrow + k0 + ac0 * 8 + 8);
        cpa16(sb + 16384 + sbo, wdh + gbo + k0);
        cpa16(sb + 20480 + sbo, wdl + gbo + k0);
    };

    float acc[2][4][4] = {};

    ldstage(0, 0); CPA_COMMIT();
    ldstage(1, 1); CPA_COMMIT();

    const int NIT = FF / 32;
    int rowA = wm * 32 + (lane & 15);
    int cA   = lane >> 4;
    int rowB = wn * 32 + ((lane >> 4) << 3) + (lane & 7);
    int cB   = (lane >> 3) & 1;
    int swA  = (rowA >> 1) & 3;
    int swB  = (rowB >> 1) & 3;

    int s = 0;
    for (int it = 0; it < NIT; it++) {
        CPA_WAIT1();
        __syncthreads();

        if (it + 2 < NIT) ldstage((s + 2 >= 3 ? s - 1 : s + 2), it + 2);
        CPA_COMMIT();

        uint32_t sb = sb_base + s * STG2;
#pragma unroll
        for (int kk = 0; kk < 2; kk++) {
            uint32_t caA = (uint32_t)(((2 * kk + cA) ^ swA) * 16);
            uint32_t ah[2][4], al[2][4];
            ldm4(ah[0], sb + (uint32_t)(rowA * 64) + caA);
            ldm4(ah[1], sb + (uint32_t)((rowA + 16) * 64) + caA);
            ldm4(al[0], sb + 8192 + (uint32_t)(rowA * 64) + caA);
            ldm4(al[1], sb + 8192 + (uint32_t)((rowA + 16) * 64) + caA);

            uint32_t caB = (uint32_t)(((2 * kk + cB) ^ swB) * 16);
#pragma unroll
            for (int half = 0; half < 2; half++) {
                uint32_t bo = (uint32_t)((rowB + half * 16) * 64) + caB;
                uint32_t bh4[4], bl4[4];
                ldm4(bh4, sb + 16384 + bo);
                ldm4(bl4, sb + 20480 + bo);
#pragma unroll
                for (int mt = 0; mt < 2; mt++)
#pragma unroll
                    for (int q = 0; q < 2; q++) {
                        int nt = half * 2 + q;
                        mma16816(acc[mt][nt], ah[mt], &bh4[q * 2]);
                        mma16816(acc[mt][nt], ah[mt], &bl4[q * 2]);
                        mma16816(acc[mt][nt], al[mt], &bh4[q * 2]);
                    }
            }
        }
        s = (s + 1 == 3) ? 0 : s + 1;
    }

#pragma unroll
    for (int mt = 0; mt < 2; mt++)
#pragma unroll
        for (int nt = 0; nt < 4; nt++) {
            int col = n0 + wn * 32 + nt * 8 + 2 * (lane & 3);
#pragma unroll
            for (int rp = 0; rp < 2; rp++) {
                int tr = wm * 32 + mt * 16 + (lane >> 2) + rp * 8;
                if (m0 + tr < ne) {
                    float2* yo = (float2*)(g_y + (size_t)(base + m0 + tr) * DIM + col);
                    *yo = make_float2(acc[mt][nt][rp * 2], acc[mt][nt][rp * 2 + 1]);
                }
            }
        }
}

// ---------------- combine -------------------------------------------------------
__global__ void k_combine(const float* __restrict__ w, float4* __restrict__ out) {
    int i = blockIdx.x * blockDim.x + threadIdx.x;
    int t = i >> 8;
    int d4 = i & 255;
    int p0 = g_pos[2 * t], p1 = g_pos[2 * t + 1];
    float w0 = (p0 < 0) ? 0.f : w[2 * t];
    float w1 = (p1 < 0) ? 0.f : w[2 * t + 1];
    int q0 = p0 < 0 ? 0 : p0, q1 = p1 < 0 ? 0 : p1;
    const float4* y4 = (const float4*)g_y;
    float4 a = y4[(size_t)q0 * 256 + d4];
    float4 b = y4[(size_t)q1 * 256 + d4];
    out[i] = make_float4(w0 * a.x + w1 * b.x, w0 * a.y + w1 * b.y,
                         w0 * a.z + w1 * b.z, w0 * a.w + w1 * b.w);
}

// ---------------- launch --------------------------------------------------------
extern "C" void kernel_launch(void* const* d_in, const int* in_sizes, int n_in,
                              void* d_out, int out_size) {
    const float* x     = (const float*)d_in[0];
    const int*   idx32 = (const int*)d_in[1];
    const float* w     = (const float*)d_in[2];
    const float* wg    = (const float*)d_in[3];
    const float* wu    = (const float*)d_in[4];
    const float* wd    = (const float*)d_in[5];
    float*       out   = (float*)d_out;

    cudaFuncSetAttribute(k_gemm1, cudaFuncAttributeMaxDynamicSharedMemorySize, 3 * STG1);
    cudaFuncSetAttribute(k_gemm2, cudaFuncAttributeMaxDynamicSharedMemorySize, 3 * STG2);

    // launch index 3 (k_gemm1) is the one ncu captures — keep it there.
    k_dispatch<<<1, 256>>>(idx32);                                  // 0
    k_cvt_x<<<(TOK * DIM / 4) / 256, 256>>>((const float4*)x);      // 1
    k_cvt_w<<<dim3(32, 32, 48), dim3(32, 8)>>>(wg, wu, wd);         // 2
    k_gemm1<<<dim3(FF / 64, CAP / 128, E_), 256, 3 * STG1>>>();     // 3  <- profiled
    k_gemm2<<<dim3(DIM / 64, CAP / 128, E_), 256, 3 * STG2>>>();    // 4
    k_combine<<<(TOK * DIM / 4) / 256, 256>>>(w, (float4*)out);     // 5
}

// round 13
// speedup vs baseline: 1.0202x; 1.0202x over previous
#include <cuda_runtime.h>
#include <cuda_bf16.h>
#include <cstdint>

#define E_   16
#define KSEL 2
#define DIM  1024
#define FF   512
#define TOK  4096
#define TKN  (TOK * KSEL)
#define CAP  2048          // per-expert capacity (matches reference C)

// ---------------- device scratch ----------------------------------------------
__device__ int g_off[E_ + 1];
__device__ int g_tok[TKN];
__device__ int g_pos[TKN];          // flat slot -> compacted pos, -1 if dropped
__device__ __align__(16) __nv_bfloat16 g_xhi[(size_t)TOK * DIM];
__device__ __align__(16) __nv_bfloat16 g_xlo[(size_t)TOK * DIM];
__device__ __align__(16) __nv_bfloat16 g_wgThi[(size_t)E_ * FF * DIM];
__device__ __align__(16) __nv_bfloat16 g_wgTlo[(size_t)E_ * FF * DIM];
__device__ __align__(16) __nv_bfloat16 g_wuThi[(size_t)E_ * FF * DIM];
__device__ __align__(16) __nv_bfloat16 g_wuTlo[(size_t)E_ * FF * DIM];
__device__ __align__(16) __nv_bfloat16 g_wdThi[(size_t)E_ * DIM * FF];
__device__ __align__(16) __nv_bfloat16 g_wdTlo[(size_t)E_ * DIM * FF];
__device__ __align__(16) __nv_bfloat16 g_hhi[(size_t)TKN * FF];
__device__ __align__(16) __nv_bfloat16 g_hlo[(size_t)TKN * FF];
__device__ __align__(16) float g_y[(size_t)TKN * DIM];

// ---------------- helpers -------------------------------------------------------
__device__ __forceinline__ uint32_t smem_u32(const void* p) {
    uint32_t a;
    asm("{ .reg .u64 t; cvta.to.shared.u64 t, %1; cvt.u32.u64 %0, t; }" : "=r"(a) : "l"(p));
    return a;
}
__device__ __forceinline__ void cpa16(uint32_t sm, const void* g) {
    asm volatile("cp.async.ca.shared.global [%0], [%1], 16;" :: "r"(sm), "l"(g));
}
#define CPA_COMMIT() asm volatile("cp.async.commit_group;" ::: "memory")
#define CPA_WAIT1()  asm volatile("cp.async.wait_group 1;" ::: "memory")

__device__ __forceinline__ void ldm4(uint32_t* r, uint32_t addr) {
    asm volatile("ldmatrix.sync.aligned.m8n8.x4.shared.b16 {%0,%1,%2,%3}, [%4];"
                 : "=r"(r[0]), "=r"(r[1]), "=r"(r[2]), "=r"(r[3]) : "r"(addr));
}
__device__ __forceinline__ void mma16816(float* c, const uint32_t* a, const uint32_t* b) {
    asm volatile(
        "mma.sync.aligned.m16n8k16.row.col.f32.bf16.bf16.f32 "
        "{%0,%1,%2,%3}, {%4,%5,%6,%7}, {%8,%9}, {%0,%1,%2,%3};"
        : "+f"(c[0]), "+f"(c[1]), "+f"(c[2]), "+f"(c[3])
        : "r"(a[0]), "r"(a[1]), "r"(a[2]), "r"(a[3]), "r"(b[0]), "r"(b[1]));
}
__device__ __forceinline__ uint32_t pack2(__nv_bfloat16 a, __nv_bfloat16 b) {
    return (uint32_t)__bfloat16_as_ushort(a) | ((uint32_t)__bfloat16_as_ushort(b) << 16);
}

// ---------------- fused dispatch (single CTA) -----------------------------------
__global__ void k_dispatch(const int* __restrict__ w32) {
    __shared__ int s_acc;
    __shared__ int s_cnt[E_];
    __shared__ int s_off[E_ + 1];
    __shared__ int s_cur[E_];
    int tid = threadIdx.x;

    if (tid == 0) s_acc = 0;
    if (tid < E_) s_cnt[tid] = 0;
    __syncthreads();

    int o = 0;
    for (int i = tid; i < TKN / 2; i += blockDim.x) o |= w32[2 * i + 1];
    atomicOr(&s_acc, o);
    __syncthreads();
    int is64 = (s_acc == 0) ? 1 : 0;

    for (int s = tid; s < TKN; s += blockDim.x) {
        int e = (is64 ? w32[2 * s] : w32[s]) & (E_ - 1);
        atomicAdd(&s_cnt[e], 1);
    }
    __syncthreads();

    if (tid == 0) {
        int acc = 0;
        for (int e = 0; e < E_; e++) {
            s_off[e] = acc;
            s_cur[e] = acc;
            g_off[e] = acc;
            acc += s_cnt[e];
        }
        s_off[E_] = acc;
        g_off[E_] = acc;
    }
    __syncthreads();

    for (int s = tid; s < TKN; s += blockDim.x) {
        int e = (is64 ? w32[2 * s] : w32[s]) & (E_ - 1);
        int p = atomicAdd(&s_cur[e], 1);
        g_tok[p] = s / KSEL;
        g_pos[s] = (p - s_off[e] < CAP) ? p : -1;
    }
}

// ---------------- conversions ---------------------------------------------------
__global__ void k_cvt_x(const float4* __restrict__ x) {
    int i = blockIdx.x * blockDim.x + threadIdx.x;
    float4 v = x[i];
    __nv_bfloat16 h0 = __float2bfloat16(v.x), h1 = __float2bfloat16(v.y),
                  h2 = __float2bfloat16(v.z), h3 = __float2bfloat16(v.w);
    __nv_bfloat16 l0 = __float2bfloat16(v.x - __bfloat162float(h0));
    __nv_bfloat16 l1 = __float2bfloat16(v.y - __bfloat162float(h1));
    __nv_bfloat16 l2 = __float2bfloat16(v.z - __bfloat162float(h2));
    __nv_bfloat16 l3 = __float2bfloat16(v.w - __bfloat162float(h3));
    ((uint2*)g_xhi)[i] = make_uint2(pack2(h0, h1), pack2(h2, h3));
    ((uint2*)g_xlo)[i] = make_uint2(pack2(l0, l1), pack2(l2, l3));
}

__global__ void k_cvt_w(const float* __restrict__ wg, const float* __restrict__ wu,
                        const float* __restrict__ wd) {
    int z = blockIdx.z, m = z >> 4, e = z & 15;
    int R = (m == 2) ? FF : DIM;
    int C = (m == 2) ? DIM : FF;
    const float* src = (m == 0 ? wg : m == 1 ? wu : wd) + (size_t)e * DIM * FF;
    __nv_bfloat16* dh = (m == 0 ? g_wgThi : m == 1 ? g_wuThi : g_wdThi) + (size_t)e * DIM * FF;
    __nv_bfloat16* dl = (m == 0 ? g_wgTlo : m == 1 ? g_wuTlo : g_wdTlo) + (size_t)e * DIM * FF;
    int c0 = blockIdx.x * 32, r0 = blockIdx.y * 32;
    if (c0 >= C || r0 >= R) return;
    __shared__ float t[32][33];
    int tx = threadIdx.x, ty = threadIdx.y;
#pragma unroll
    for (int i = 0; i < 4; i++)
        t[ty + i * 8][tx] = src[(size_t)(r0 + ty + i * 8) * C + c0 + tx];
    __syncthreads();
#pragma unroll
    for (int i = 0; i < 4; i++) {
        float v = t[tx][ty + i * 8];
        __nv_bfloat16 h = __float2bfloat16(v);
        __nv_bfloat16 l = __float2bfloat16(v - __bfloat162float(h));
        size_t o = (size_t)(c0 + ty + i * 8) * R + r0 + tx;
        dh[o] = h;
        dl[o] = l;
    }
}

// ---------------- GEMM1: h = silu(X Wg)*(X Wu), bf16x3 HMMA ---------------------
// R10 structure (BK=16, 3-stage, swizzle) + term-outer MMA order to break
// dependent accumulator chains. Per-accumulator term order unchanged (hh,hl,lh)
// -> bit-identical numerics.
__global__ __launch_bounds__(256, 2) void k_gemm1() {
    __shared__ __align__(16) char sbuf[3][16384];

    int e = blockIdx.z;
    int base = g_off[e], ne = g_off[e + 1] - base;
    int m0 = blockIdx.y * 128;
    if (m0 >= ne) return;
    int n0 = blockIdx.x * 64;

    int tid = threadIdx.x, lane = tid & 31, wid = tid >> 5;
    int wm = wid >> 1, wn = wid & 1;

    size_t wb = ((size_t)e * FF + n0) * DIM;
    const __nv_bfloat16* wgh = g_wgThi + wb;
    const __nv_bfloat16* wgl = g_wgTlo + wb;
    const __nv_bfloat16* wuh = g_wuThi + wb;
    const __nv_bfloat16* wul = g_wuTlo + wb;

    int ar = tid >> 1, aci = tid & 1;
    int arow_ = m0 + ar; if (arow_ >= ne) arow_ = ne - 1;
    size_t tokrow = (size_t)g_tok[base + arow_] * DIM;
    int bh_ = tid >> 7, br = (tid >> 1) & 63, bci = tid & 1;

    uint32_t sa = ar * 32 + (aci ^ ((ar >> 2) & 1)) * 16;
    uint32_t sB = br * 32 + (bci ^ ((br >> 2) & 1)) * 16;

    uint32_t sb_base = smem_u32(sbuf);
    auto ldstage = [&](int s, int it) {
        uint32_t sb = sb_base + s * 16384;
        int k0 = it * 16;
        cpa16(sb + sa, g_xhi + tokrow + k0 + aci * 8);
        cpa16(sb + 4096 + sa, g_xlo + tokrow + k0 + aci * 8);
        size_t gb = (size_t)br * DIM + k0 + bci * 8;
        cpa16(sb + 8192 + bh_ * 2048 + sB, (bh_ ? wgl : wgh) + gb);
        cpa16(sb + 12288 + bh_ * 2048 + sB, (bh_ ? wul : wuh) + gb);
    };

    float acc_g[2][4][4] = {};
    float acc_u[2][4][4] = {};

    ldstage(0, 0); CPA_COMMIT();
    ldstage(1, 1); CPA_COMMIT();

    const int NIT = DIM / 16;
    uint32_t aoff = (wm * 32 + (lane & 15)) * 32 +
                    (((lane >> 4) ^ ((lane >> 2) & 1)) * 16);
    uint32_t bbase = (wn * 32 + ((lane >> 4) << 3) + (lane & 7)) * 32 +
                     ((((lane >> 3) & 1) ^ ((lane >> 2) & 1)) * 16);

    int s = 0;
    for (int it = 0; it < NIT; it++) {
        CPA_WAIT1();
        __syncthreads();

        if (it + 2 < NIT) ldstage((s + 2 >= 3 ? s - 1 : s + 2), it + 2);
        CPA_COMMIT();

        uint32_t sb = sb_base + s * 16384;
        uint32_t ah[2][4], al[2][4];
        ldm4(ah[0], sb + aoff);
        ldm4(ah[1], sb + aoff + 512);
        ldm4(al[0], sb + 4096 + aoff);
        ldm4(al[1], sb + 4096 + aoff + 512);

#pragma unroll
        for (int half = 0; half < 2; half++) {
            uint32_t bo = bbase + half * 512;
            uint32_t bgh[4], bgl[4], buh[4], bul[4];
            ldm4(bgh, sb + 8192 + bo);
            ldm4(bgl, sb + 10240 + bo);
            ldm4(buh, sb + 12288 + bo);
            ldm4(bul, sb + 14336 + bo);
            // term-outer: each accumulator is revisited only every 8 MMAs
#pragma unroll
            for (int term = 0; term < 3; term++) {
#pragma unroll
                for (int mt = 0; mt < 2; mt++)
#pragma unroll
                    for (int q = 0; q < 2; q++) {
                        int nt = half * 2 + q;
                        const uint32_t* a  = (term == 2) ? al[mt] : ah[mt];
                        const uint32_t* bg = (term == 1) ? &bgl[q * 2] : &bgh[q * 2];
                        const uint32_t* bu = (term == 1) ? &bul[q * 2] : &buh[q * 2];
                        mma16816(acc_g[mt][nt], a, bg);
                        mma16816(acc_u[mt][nt], a, bu);
                    }
            }
        }
        s = (s + 1 == 3) ? 0 : s + 1;
    }

#pragma unroll
    for (int mt = 0; mt < 2; mt++)
#pragma unroll
        for (int nt = 0; nt < 4; nt++) {
            int col = n0 + wn * 32 + nt * 8 + 2 * (lane & 3);
#pragma unroll
            for (int rp = 0; rp < 2; rp++) {
                int tr = wm * 32 + mt * 16 + (lane >> 2) + rp * 8;
                if (m0 + tr < ne) {
                    float gg0 = acc_g[mt][nt][rp * 2], gg1 = acc_g[mt][nt][rp * 2 + 1];
                    float uu0 = acc_u[mt][nt][rp * 2], uu1 = acc_u[mt][nt][rp * 2 + 1];
                    float h0 = gg0 / (1.f + __expf(-gg0)) * uu0;
                    float h1 = gg1 / (1.f + __expf(-gg1)) * uu1;
                    __nv_bfloat16 h0h = __float2bfloat16(h0);
                    __nv_bfloat16 h1h = __float2bfloat16(h1);
                    __nv_bfloat16 h0l = __float2bfloat16(h0 - __bfloat162float(h0h));
                    __nv_bfloat16 h1l = __float2bfloat16(h1 - __bfloat162float(h1h));
                    size_t o = (size_t)(base + m0 + tr) * FF + col;
                    *(uint32_t*)(g_hhi + o) = pack2(h0h, h1h);
                    *(uint32_t*)(g_hlo + o) = pack2(h0l, h1l);
                }
            }
        }
}

// ---------------- GEMM2: y = h Wd, bf16x3 HMMA ----------------------------------
__global__ __launch_bounds__(256, 2) void k_gemm2() {
    __shared__ __align__(16) char sbuf[3][12288];

    int e = blockIdx.z;
    int base = g_off[e], ne = g_off[e + 1] - base;
    int m0 = blockIdx.y * 128;
    if (m0 >= ne) return;
    int n0 = blockIdx.x * 64;

    int tid = threadIdx.x, lane = tid & 31, wid = tid >> 5;
    int wm = wid >> 1, wn = wid & 1;

    size_t wb = ((size_t)e * DIM + n0) * FF;
    const __nv_bfloat16* wdh = g_wdThi + wb;
    const __nv_bfloat16* wdl = g_wdTlo + wb;

    int ar = tid >> 1, aci = tid & 1;
    int arr = m0 + ar; if (arr >= ne) arr = ne - 1;
    size_t arow = (size_t)(base + arr) * FF;
    int bh_ = tid >> 7, br = (tid >> 1) & 63, bci = tid & 1;

    uint32_t sa = ar * 32 + (aci ^ ((ar >> 2) & 1)) * 16;
    uint32_t sB = br * 32 + (bci ^ ((br >> 2) & 1)) * 16;

    uint32_t sb_base = smem_u32(sbuf);
    auto ldstage = [&](int s, int it) {
        uint32_t sb = sb_base + s * 12288;
        int k0 = it * 16;
        cpa16(sb + sa, g_hhi + arow + k0 + aci * 8);
        cpa16(sb + 4096 + sa, g_hlo + arow + k0 + aci * 8);
        size_t gb = (size_t)br * FF + k0 + bci * 8;
        cpa16(sb + 8192 + bh_ * 2048 + sB, (bh_ ? wdl : wdh) + gb);
    };

    float acc[2][4][4] = {};

    ldstage(0, 0); CPA_COMMIT();
    ldstage(1, 1); CPA_COMMIT();

    const int NIT = FF / 16;
    uint32_t aoff = (wm * 32 + (lane & 15)) * 32 +
                    (((lane >> 4) ^ ((lane >> 2) & 1)) * 16);
    uint32_t bbase = (wn * 32 + ((lane >> 4) << 3) + (lane & 7)) * 32 +
                     ((((lane >> 3) & 1) ^ ((lane >> 2) & 1)) * 16);

    int s = 0;
    for (int it = 0; it < NIT; it++) {
        CPA_WAIT1();
        __syncthreads();

        if (it + 2 < NIT) ldstage((s + 2 >= 3 ? s - 1 : s + 2), it + 2);
        CPA_COMMIT();

        uint32_t sb = sb_base + s * 12288;
        uint32_t ah[2][4], al[2][4];
        ldm4(ah[0], sb + aoff);
        ldm4(ah[1], sb + aoff + 512);
        ldm4(al[0], sb + 4096 + aoff);
        ldm4(al[1], sb + 4096 + aoff + 512);

#pragma unroll
        for (int half = 0; half < 2; half++) {
            uint32_t bo = bbase + half * 512;
            uint32_t bh4[4], bl4[4];
            ldm4(bh4, sb + 8192 + bo);
            ldm4(bl4, sb + 10240 + bo);
            // term-outer ordering; per-accumulator order still hh, hl, lh
#pragma unroll
            for (int term = 0; term < 3; term++) {
#pragma unroll
                for (int mt = 0; mt < 2; mt++)
#pragma unroll
                    for (int q = 0; q < 2; q++) {
                        int nt = half * 2 + q;
                        const uint32_t* a = (term == 2) ? al[mt] : ah[mt];
                        const uint32_t* b = (term == 1) ? &bl4[q * 2] : &bh4[q * 2];
                        mma16816(acc[mt][nt], a, b);
                    }
            }
        }
        s = (s + 1 == 3) ? 0 : s + 1;
    }

#pragma unroll
    for (int mt = 0; mt < 2; mt++)
#pragma unroll
        for (int nt = 0; nt < 4; nt++) {
            int col = n0 + wn * 32 + nt * 8 + 2 * (lane & 3);
#pragma unroll
            for (int rp = 0; rp < 2; rp++) {
                int tr = wm * 32 + mt * 16 + (lane >> 2) + rp * 8;
                if (m0 + tr < ne) {
                    float2* yo = (float2*)(g_y + (size_t)(base + m0 + tr) * DIM + col);
                    *yo = make_float2(acc[mt][nt][rp * 2], acc[mt][nt][rp * 2 + 1]);
                }
            }
        }
}

// ---------------- combine -------------------------------------------------------
__global__ void k_combine(const float* __restrict__ w, float4* __restrict__ out) {
    int i = blockIdx.x * blockDim.x + threadIdx.x;
    int t = i >> 8;
    int d4 = i & 255;
    int p0 = g_pos[2 * t], p1 = g_pos[2 * t + 1];
    float w0 = (p0 < 0) ? 0.f : w[2 * t];
    float w1 = (p1 < 0) ? 0.f : w[2 * t + 1];
    int q0 = p0 < 0 ? 0 : p0, q1 = p1 < 0 ? 0 : p1;
    const float4* y4 = (const float4*)g_y;
    float4 a = y4[(size_t)q0 * 256 + d4];
    float4 b = y4[(size_t)q1 * 256 + d4];
    out[i] = make_float4(w0 * a.x + w1 * b.x, w0 * a.y + w1 * b.y,
                         w0 * a.z + w1 * b.z, w0 * a.w + w1 * b.w);
}

// ---------------- launch --------------------------------------------------------
extern "C" void kernel_launch(void* const* d_in, const int* in_sizes, int n_in,
                              void* d_out, int out_size) {
    const float* x     = (const float*)d_in[0];
    const int*   idx32 = (const int*)d_in[1];
    const float* w     = (const float*)d_in[2];
    const float* wg    = (const float*)d_in[3];
    const float* wu    = (const float*)d_in[4];
    const float* wd    = (const float*)d_in[5];
    float*       out   = (float*)d_out;

    // launch index 3 (k_gemm1) is the one ncu captures — keep it there.
    k_dispatch<<<1, 256>>>(idx32);                                  // 0
    k_cvt_x<<<(TOK * DIM / 4) / 256, 256>>>((const float4*)x);      // 1
    k_cvt_w<<<dim3(32, 32, 48), dim3(32, 8)>>>(wg, wu, wd);         // 2
    k_gemm1<<<dim3(FF / 64, CAP / 128, E_), 256>>>();               // 3  <- profiled
    k_gemm2<<<dim3(DIM / 64, CAP / 128, E_), 256>>>();              // 4
    k_combine<<<(TOK * DIM / 4) / 256, 256>>>(w, (float4*)out);     // 5
}

// round 16
// speedup vs baseline: 1.2720x; 1.2468x over previous
#include <cuda_runtime.h>
#include <cuda_fp16.h>
#include <cstdint>

#define E_   16
#define KSEL 2
#define DIM  1024
#define FF   512
#define TOK  4096
#define TKN  (TOK * KSEL)
#define CAP  2048          // per-expert capacity (matches reference C)

// ---------------- device scratch ----------------------------------------------
__device__ int g_off[E_ + 1];
__device__ int g_tok[TKN];
__device__ int g_pos[TKN];          // flat slot -> compacted pos, -1 if dropped
__device__ __align__(16) __half g_xh[(size_t)TOK * DIM];
__device__ __align__(16) __half g_wgTh[(size_t)E_ * FF * DIM];
__device__ __align__(16) __half g_wgTl[(size_t)E_ * FF * DIM];
__device__ __align__(16) __half g_wuTh[(size_t)E_ * FF * DIM];
__device__ __align__(16) __half g_wuTl[(size_t)E_ * FF * DIM];
__device__ __align__(16) __half g_wdTh[(size_t)E_ * DIM * FF];
__device__ __align__(16) __half g_wdTl[(size_t)E_ * DIM * FF];
__device__ __align__(16) __half g_hh[(size_t)TKN * FF];
__device__ __align__(16) float g_y[(size_t)TKN * DIM];

// ---------------- helpers -------------------------------------------------------
__device__ __forceinline__ uint32_t smem_u32(const void* p) {
    uint32_t a;
    asm("{ .reg .u64 t; cvta.to.shared.u64 t, %1; cvt.u32.u64 %0, t; }" : "=r"(a) : "l"(p));
    return a;
}
__device__ __forceinline__ void cpa16(uint32_t sm, const void* g) {
    asm volatile("cp.async.ca.shared.global [%0], [%1], 16;" :: "r"(sm), "l"(g));
}
#define CPA_COMMIT() asm volatile("cp.async.commit_group;" ::: "memory")
#define CPA_WAIT1()  asm volatile("cp.async.wait_group 1;" ::: "memory")

__device__ __forceinline__ void ldm4(uint32_t* r, uint32_t addr) {
    asm volatile("ldmatrix.sync.aligned.m8n8.x4.shared.b16 {%0,%1,%2,%3}, [%4];"
                 : "=r"(r[0]), "=r"(r[1]), "=r"(r[2]), "=r"(r[3]) : "r"(addr));
}
__device__ __forceinline__ void mma16816(float* c, const uint32_t* a, const uint32_t* b) {
    asm volatile(
        "mma.sync.aligned.m16n8k16.row.col.f32.f16.f16.f32 "
        "{%0,%1,%2,%3}, {%4,%5,%6,%7}, {%8,%9}, {%0,%1,%2,%3};"
        : "+f"(c[0]), "+f"(c[1]), "+f"(c[2]), "+f"(c[3])
        : "r"(a[0]), "r"(a[1]), "r"(a[2]), "r"(a[3]), "r"(b[0]), "r"(b[1]));
}
__device__ __forceinline__ uint32_t pack2h(__half a, __half b) {
    return (uint32_t)__half_as_ushort(a) | ((uint32_t)__half_as_ushort(b) << 16);
}

// ---------------- fused dispatch (single CTA) -----------------------------------
__global__ void k_dispatch(const int* __restrict__ w32) {
    __shared__ int s_acc;
    __shared__ int s_cnt[E_];
    __shared__ int s_off[E_ + 1];
    __shared__ int s_cur[E_];
    int tid = threadIdx.x;

    if (tid == 0) s_acc = 0;
    if (tid < E_) s_cnt[tid] = 0;
    __syncthreads();

    int o = 0;
    for (int i = tid; i < TKN / 2; i += blockDim.x) o |= w32[2 * i + 1];
    atomicOr(&s_acc, o);
    __syncthreads();
    int is64 = (s_acc == 0) ? 1 : 0;

    for (int s = tid; s < TKN; s += blockDim.x) {
        int e = (is64 ? w32[2 * s] : w32[s]) & (E_ - 1);
        atomicAdd(&s_cnt[e], 1);
    }
    __syncthreads();

    if (tid == 0) {
        int acc = 0;
        for (int e = 0; e < E_; e++) {
            s_off[e] = acc;
            s_cur[e] = acc;
            g_off[e] = acc;
            acc += s_cnt[e];
        }
        s_off[E_] = acc;
        g_off[E_] = acc;
    }
    __syncthreads();

    for (int s = tid; s < TKN; s += blockDim.x) {
        int e = (is64 ? w32[2 * s] : w32[s]) & (E_ - 1);
        int p = atomicAdd(&s_cur[e], 1);
        g_tok[p] = s / KSEL;
        g_pos[s] = (p - s_off[e] < CAP) ? p : -1;
    }
}

// ---------------- conversions ---------------------------------------------------
__global__ void k_cvt_x(const float4* __restrict__ x) {
    int i = blockIdx.x * blockDim.x + threadIdx.x;
    float4 v = x[i];
    ((uint2*)g_xh)[i] = make_uint2(pack2h(__float2half(v.x), __float2half(v.y)),
                                   pack2h(__float2half(v.z), __float2half(v.w)));
}

__global__ void k_cvt_w(const float* __restrict__ wg, const float* __restrict__ wu,
                        const float* __restrict__ wd) {
    int z = blockIdx.z, m = z >> 4, e = z & 15;
    int R = (m == 2) ? FF : DIM;
    int C = (m == 2) ? DIM : FF;
    const float* src = (m == 0 ? wg : m == 1 ? wu : wd) + (size_t)e * DIM * FF;
    __half* dh = (m == 0 ? g_wgTh : m == 1 ? g_wuTh : g_wdTh) + (size_t)e * DIM * FF;
    __half* dl = (m == 0 ? g_wgTl : m == 1 ? g_wuTl : g_wdTl) + (size_t)e * DIM * FF;
    int c0 = blockIdx.x * 32, r0 = blockIdx.y * 32;
    if (c0 >= C || r0 >= R) return;
    __shared__ float t[32][33];
    int tx = threadIdx.x, ty = threadIdx.y;
#pragma unroll
    for (int i = 0; i < 4; i++)
        t[ty + i * 8][tx] = src[(size_t)(r0 + ty + i * 8) * C + c0 + tx];
    __syncthreads();
#pragma unroll
    for (int i = 0; i < 4; i++) {
        float v = t[tx][ty + i * 8];
        __half h = __float2half(v);
        __half l = __float2half(v - __half2float(h));
        size_t o = (size_t)(c0 + ty + i * 8) * R + r0 + tx;
        dh[o] = h;
        dl[o] = l;
    }
}

// ---------------- GEMM1: h = silu(X Wg)*(X Wu), fp16x2 HMMA ---------------------
// stage (12KB): A 4K | Bgh 2K | Bgl 2K | Buh 2K | Bul 2K  (32B rows, swizzled)
#define STG1 12288
__global__ __launch_bounds__(256, 2) void k_gemm1() {
    __shared__ __align__(16) char sbuf[3][STG1];

    int e = blockIdx.z;
    int base = g_off[e], ne = g_off[e + 1] - base;
    int m0 = blockIdx.y * 128;
    if (m0 >= ne) return;
    int n0 = blockIdx.x * 64;

    int tid = threadIdx.x, lane = tid & 31, wid = tid >> 5;
    int wm = wid >> 1, wn = wid & 1;

    size_t wb = ((size_t)e * FF + n0) * DIM;
    const __half* wgh = g_wgTh + wb;
    const __half* wgl = g_wgTl + wb;
    const __half* wuh = g_wuTh + wb;
    const __half* wul = g_wuTl + wb;

    int ar = tid >> 1, aci = tid & 1;
    int arow_ = m0 + ar; if (arow_ >= ne) arow_ = ne - 1;
    size_t tokrow = (size_t)g_tok[base + arow_] * DIM;
    int bh_ = tid >> 7, br = (tid >> 1) & 63, bci = tid & 1;

    uint32_t sa = ar * 32 + (aci ^ ((ar >> 2) & 1)) * 16;
    uint32_t sB = br * 32 + (bci ^ ((br >> 2) & 1)) * 16;

    uint32_t sb_base = smem_u32(sbuf);
    auto ldstage = [&](int s, int it) {
        uint32_t sb = sb_base + s * STG1;
        int k0 = it * 16;
        cpa16(sb + sa, g_xh + tokrow + k0 + aci * 8);
        size_t gb = (size_t)br * DIM + k0 + bci * 8;
        cpa16(sb + 4096 + bh_ * 2048 + sB, (bh_ ? wgl : wgh) + gb);
        cpa16(sb + 8192 + bh_ * 2048 + sB, (bh_ ? wul : wuh) + gb);
    };

    float acc_g[2][4][4] = {};
    float acc_u[2][4][4] = {};

    ldstage(0, 0); CPA_COMMIT();
    ldstage(1, 1); CPA_COMMIT();

    const int NIT = DIM / 16;
    uint32_t aoff = (wm * 32 + (lane & 15)) * 32 +
                    (((lane >> 4) ^ ((lane >> 2) & 1)) * 16);
    uint32_t bbase = (wn * 32 + ((lane >> 4) << 3) + (lane & 7)) * 32 +
                     ((((lane >> 3) & 1) ^ ((lane >> 2) & 1)) * 16);

    int s = 0;
    for (int it = 0; it < NIT; it++) {
        CPA_WAIT1();
        __syncthreads();

        if (it + 2 < NIT) ldstage((s + 2 >= 3 ? s - 1 : s + 2), it + 2);
        CPA_COMMIT();

        uint32_t sb = sb_base + s * STG1;
        uint32_t ah[2][4];
        ldm4(ah[0], sb + aoff);
        ldm4(ah[1], sb + aoff + 512);

#pragma unroll
        for (int half = 0; half < 2; half++) {
            uint32_t bo = bbase + half * 512;
            uint32_t bgh[4], bgl[4], buh[4], bul[4];
            ldm4(bgh, sb + 4096 + bo);
            ldm4(bgl, sb + 6144 + bo);
            ldm4(buh, sb + 8192 + bo);
            ldm4(bul, sb + 10240 + bo);
            // term-outer; per-accumulator order hi then lo (deterministic)
#pragma unroll
            for (int term = 0; term < 2; term++) {
#pragma unroll
                for (int mt = 0; mt < 2; mt++)
#pragma unroll
                    for (int q = 0; q < 2; q++) {
                        int nt = half * 2 + q;
                        const uint32_t* bg = term ? &bgl[q * 2] : &bgh[q * 2];
                        const uint32_t* bu = term ? &bul[q * 2] : &buh[q * 2];
                        mma16816(acc_g[mt][nt], ah[mt], bg);
                        mma16816(acc_u[mt][nt], ah[mt], bu);
                    }
            }
        }
        s = (s + 1 == 3) ? 0 : s + 1;
    }

#pragma unroll
    for (int mt = 0; mt < 2; mt++)
#pragma unroll
        for (int nt = 0; nt < 4; nt++) {
            int col = n0 + wn * 32 + nt * 8 + 2 * (lane & 3);
#pragma unroll
            for (int rp = 0; rp < 2; rp++) {
                int tr = wm * 32 + mt * 16 + (lane >> 2) + rp * 8;
                if (m0 + tr < ne) {
                    float gg0 = acc_g[mt][nt][rp * 2], gg1 = acc_g[mt][nt][rp * 2 + 1];
                    float uu0 = acc_u[mt][nt][rp * 2], uu1 = acc_u[mt][nt][rp * 2 + 1];
                    float h0 = gg0 / (1.f + __expf(-gg0)) * uu0;
                    float h1 = gg1 / (1.f + __expf(-gg1)) * uu1;
                    size_t o = (size_t)(base + m0 + tr) * FF + col;
                    *(uint32_t*)(g_hh + o) = pack2h(__float2half(h0), __float2half(h1));
                }
            }
        }
}

// ---------------- GEMM2: y = h Wd, fp16x2 HMMA ----------------------------------
// stage (8KB): A 4K | Bh 2K | Bl 2K
#define STG2 8192
__global__ __launch_bounds__(256, 3) void k_gemm2() {
    __shared__ __align__(16) char sbuf[3][STG2];

    int e = blockIdx.z;
    int base = g_off[e], ne = g_off[e + 1] - base;
    int m0 = blockIdx.y * 128;
    if (m0 >= ne) return;
    int n0 = blockIdx.x * 64;

    int tid = threadIdx.x, lane = tid & 31, wid = tid >> 5;
    int wm = wid >> 1, wn = wid & 1;

    size_t wb = ((size_t)e * DIM + n0) * FF;
    const __half* wdh = g_wdTh + wb;
    const __half* wdl = g_wdTl + wb;

    int ar = tid >> 1, aci = tid & 1;
    int arr = m0 + ar; if (arr >= ne) arr = ne - 1;
    size_t arow = (size_t)(base + arr) * FF;
    int bh_ = tid >> 7, br = (tid >> 1) & 63, bci = tid & 1;

    uint32_t sa = ar * 32 + (aci ^ ((ar >> 2) & 1)) * 16;
    uint32_t sB = br * 32 + (bci ^ ((br >> 2) & 1)) * 16;

    uint32_t sb_base = smem_u32(sbuf);
    auto ldstage = [&](int s, int it) {
        uint32_t sb = sb_base + s * STG2;
        int k0 = it * 16;
        cpa16(sb + sa, g_hh + arow + k0 + aci * 8);
        size_t gb = (size_t)br * FF + k0 + bci * 8;
        cpa16(sb + 4096 + bh_ * 2048 + sB, (bh_ ? wdl : wdh) + gb);
    };

    float acc[2][4][4] = {};

    ldstage(0, 0); CPA_COMMIT();
    ldstage(1, 1); CPA_COMMIT();

    const int NIT = FF / 16;
    uint32_t aoff = (wm * 32 + (lane & 15)) * 32 +
                    (((lane >> 4) ^ ((lane >> 2) & 1)) * 16);
    uint32_t bbase = (wn * 32 + ((lane >> 4) << 3) + (lane & 7)) * 32 +
                     ((((lane >> 3) & 1) ^ ((lane >> 2) & 1)) * 16);

    int s = 0;
    for (int it = 0; it < NIT; it++) {
        CPA_WAIT1();
        __syncthreads();

        if (it + 2 < NIT) ldstage((s + 2 >= 3 ? s - 1 : s + 2), it + 2);
        CPA_COMMIT();

        uint32_t sb = sb_base + s * STG2;
        uint32_t ah[2][4];
        ldm4(ah[0], sb + aoff);
        ldm4(ah[1], sb + aoff + 512);

#pragma unroll
        for (int half = 0; half < 2; half++) {
            uint32_t bo = bbase + half * 512;
            uint32_t bh4[4], bl4[4];
            ldm4(bh4, sb + 4096 + bo);
            ldm4(bl4, sb + 6144 + bo);
#pragma unroll
            for (int term = 0; term < 2; term++) {
#pragma unroll
                for (int mt = 0; mt < 2; mt++)
#pragma unroll
                    for (int q = 0; q < 2; q++) {
                        int nt = half * 2 + q;
                        const uint32_t* b = term ? &bl4[q * 2] : &bh4[q * 2];
                        mma16816(acc[mt][nt], ah[mt], b);
                    }
            }
        }
        s = (s + 1 == 3) ? 0 : s + 1;
    }

#pragma unroll
    for (int mt = 0; mt < 2; mt++)
#pragma unroll
        for (int nt = 0; nt < 4; nt++) {
            int col = n0 + wn * 32 + nt * 8 + 2 * (lane & 3);
#pragma unroll
            for (int rp = 0; rp < 2; rp++) {
                int tr = wm * 32 + mt * 16 + (lane >> 2) + rp * 8;
                if (m0 + tr < ne) {
                    float2* yo = (float2*)(g_y + (size_t)(base + m0 + tr) * DIM + col);
                    *yo = make_float2(acc[mt][nt][rp * 2], acc[mt][nt][rp * 2 + 1]);
                }
            }
        }
}

// ---------------- combine -------------------------------------------------------
__global__ void k_combine(const float* __restrict__ w, float4* __restrict__ out) {
    int i = blockIdx.x * blockDim.x + threadIdx.x;
    int t = i >> 8;
    int d4 = i & 255;
    int p0 = g_pos[2 * t], p1 = g_pos[2 * t + 1];
    float w0 = (p0 < 0) ? 0.f : w[2 * t];
    float w1 = (p1 < 0) ? 0.f : w[2 * t + 1];
    int q0 = p0 < 0 ? 0 : p0, q1 = p1 < 0 ? 0 : p1;
    const float4* y4 = (const float4*)g_y;
    float4 a = y4[(size_t)q0 * 256 + d4];
    float4 b = y4[(size_t)q1 * 256 + d4];
    out[i] = make_float4(w0 * a.x + w1 * b.x, w0 * a.y + w1 * b.y,
                         w0 * a.z + w1 * b.z, w0 * a.w + w1 * b.w);
}

// ---------------- launch --------------------------------------------------------
extern "C" void kernel_launch(void* const* d_in, const int* in_sizes, int n_in,
                              void* d_out, int out_size) {
    const float* x     = (const float*)d_in[0];
    const int*   idx32 = (const int*)d_in[1];
    const float* w     = (const float*)d_in[2];
    const float* wg    = (const float*)d_in[3];
    const float* wu    = (const float*)d_in[4];
    const float* wd    = (const float*)d_in[5];
    float*       out   = (float*)d_out;

    // launch index 3 (k_gemm1) is the one ncu captures — keep it there.
    k_dispatch<<<1, 256>>>(idx32);                                  // 0
    k_cvt_x<<<(TOK * DIM / 4) / 256, 256>>>((const float4*)x);      // 1
    k_cvt_w<<<dim3(32, 32, 48), dim3(32, 8)>>>(wg, wu, wd);         // 2
    k_gemm1<<<dim3(FF / 64, CAP / 128, E_), 256>>>();               // 3  <- profiled
    k_gemm2<<<dim3(DIM / 64, CAP / 128, E_), 256>>>();              // 4
    k_combine<<<(TOK * DIM / 4) / 256, 256>>>(w, (float4*)out);     // 5
}